// round 13
// baseline (speedup 1.0000x reference)
#include <cuda_runtime.h>
#include <cstdint>

typedef unsigned int u32;
typedef unsigned long long u64;

#define NQ    256
#define DIM   128
#define NBANK 500000
#define TOPK  32

#define TILE_M 64
#define TILE_N 64
#define KSTEP  64
#define GT     256
#define PAD_STRIDE 68   // 64 + 4 floats pad

// -------- device scratch (static; allocation-free per harness rules) --------
// CRITICAL: these are ONLY referenced from device code. Passing a __device__
// symbol as a kernel argument from host passes the HOST shadow address; on
// GB300 (ATS, pageableMemoryAccess=1) such writes land in host memory without
// faulting -- that was the R10-R12 bug.
__device__ float g_sims[(size_t)NQ * NBANK];   // 512 MB
__device__ float g_newctx[NQ * DIM];
__device__ int   g_cixs[NQ * TOPK];

// ---------------------------------------------------------------------------
__device__ __forceinline__ u64 mkkey(float v, u32 n) {
    u32 u = __float_as_uint(v);
    u = (u & 0x80000000u) ? ~u : (u | 0x80000000u);   // monotonic float key
    return ((u64)u << 32) | (u32)(~n);                // ties: smaller idx wins
}

// ---------------------------------------------------------------------------
// g_sims[q][n] = sum_d A[q][d]*B[n][d].
// useNewCtx: A = g_newctx (device global) else Aparam (harness pointer).
// lane -> n (coalesced), warp -> q.
__global__ __launch_bounds__(GT)
void gemm_kernel(const float* __restrict__ Aparam, const float* __restrict__ B,
                 int n_rows, int useNewCtx)
{
    __shared__ float Af[TILE_M * PAD_STRIDE];   // 17,408 B
    __shared__ float Bf[TILE_N * PAD_STRIDE];   // 17,408 B

    const float* A = useNewCtx ? g_newctx : Aparam;

    const int tid  = threadIdx.x;
    const int lane = tid & 31;
    const int w    = tid >> 5;            // warp 0..7
    const int n0   = blockIdx.x * TILE_N;
    const int q0   = blockIdx.y * TILE_M;

    float acc[8][2];
    #pragma unroll
    for (int i = 0; i < 8; ++i) { acc[i][0] = 0.f; acc[i][1] = 0.f; }

    for (int s = 0; s < 2; ++s) {         // two K halves of 64
        const int kbase = s * KSTEP;
        __syncthreads();                  // protect smem reuse across halves
        #pragma unroll
        for (int it = 0; it < 4; ++it) {  // A half-tile [64][64]
            int idx = tid + GT * it;      // 0..1023 float4 slots
            int r = idx >> 4, c4 = idx & 15;
            float4 v = *(const float4*)(A + (size_t)(q0 + r) * DIM + kbase + 4 * c4);
            *(float4*)(Af + r * PAD_STRIDE + 4 * c4) = v;
        }
        #pragma unroll
        for (int it = 0; it < 4; ++it) {  // B half-tile [64][64], zero-padded
            int idx = tid + GT * it;
            int r = idx >> 4, c4 = idx & 15;
            float4 v = make_float4(0.f, 0.f, 0.f, 0.f);
            if (n0 + r < n_rows)
                v = *(const float4*)(B + (size_t)(n0 + r) * DIM + kbase + 4 * c4);
            *(float4*)(Bf + r * PAD_STRIDE + 4 * c4) = v;
        }
        __syncthreads();

        #pragma unroll 4
        for (int k4 = 0; k4 < 16; ++k4) { // 4 K values per step
            float4 b0 = *(const float4*)(Bf + (lane     ) * PAD_STRIDE + 4 * k4);
            float4 b1 = *(const float4*)(Bf + (lane + 32) * PAD_STRIDE + 4 * k4);
            #pragma unroll
            for (int i = 0; i < 8; ++i) {
                float4 a = *(const float4*)(Af + (w + 8 * i) * PAD_STRIDE + 4 * k4);
                acc[i][0] += a.x * b0.x + a.y * b0.y + a.z * b0.z + a.w * b0.w;
                acc[i][1] += a.x * b1.x + a.y * b1.y + a.z * b1.z + a.w * b1.w;
            }
        }
    }

    #pragma unroll
    for (int i = 0; i < 8; ++i) {
        int q = q0 + w + 8 * i;
        #pragma unroll
        for (int j = 0; j < 2; ++j) {
            int gn = n0 + lane + 32 * j;
            if (gn < n_rows)
                g_sims[(size_t)q * n_rows + gn] = acc[i][j];
        }
    }
}

// ---------------------------------------------------------------------------
// Exact per-query top-32 of g_sims row blockIdx.x. 256 threads.
// useCixs==1 -> write int32 indices into device-global g_cixs (hop 1).
// useCixs==0 -> write (float)index into outFloat = d_out (hop 2; harness
//               validates d_out as float32, proven by R10's metric shift).
__global__ __launch_bounds__(256)
void topk_kernel(float* __restrict__ outFloat, int n_rows, int useCixs)
{
    const int q   = blockIdx.x;
    const int tid = threadIdx.x;
    const float4* row = (const float4*)(g_sims + (size_t)q * n_rows);
    const int n4 = n_rows >> 2;           // 500000/4 = 125000 exact

    u64 loc[TOPK];                        // unsorted local top-32 + tracked min
    #pragma unroll
    for (int j = 0; j < TOPK; ++j) loc[j] = 0ull;
    u64 kmin = 0ull;
    int minpos = 0;

    for (int i = tid; i < n4; i += 256) {
        float4 v = row[i];
        u32 base = (u32)i << 2;
        float vv[4] = {v.x, v.y, v.z, v.w};
        #pragma unroll
        for (int c = 0; c < 4; ++c) {
            u64 key = mkkey(vv[c], base + c);
            if (key > kmin) {
                loc[minpos] = key;
                kmin = loc[0]; minpos = 0;
                #pragma unroll
                for (int j = 1; j < TOPK; ++j)
                    if (loc[j] < kmin) { kmin = loc[j]; minpos = j; }
            }
        }
    }

    __shared__ u64 red[256];              // 32 rounds of block max-extraction
    for (int r = 0; r < TOPK; ++r) {
        u64 mymax = loc[0]; int mp = 0;
        #pragma unroll
        for (int j = 1; j < TOPK; ++j)
            if (loc[j] > mymax) { mymax = loc[j]; mp = j; }
        red[tid] = mymax;
        __syncthreads();
        for (int s = 128; s > 0; s >>= 1) {
            if (tid < s) { u64 o = red[tid + s]; if (o > red[tid]) red[tid] = o; }
            __syncthreads();
        }
        u64 win = red[0];
        __syncthreads();
        if (mymax == win) loc[mp] = 0ull; // keys unique -> exactly one remover
        if (tid == 0) {
            int idx = (int)(~(u32)(win & 0xffffffffu));
            if (useCixs) g_cixs[q * TOPK + r] = idx;      // device global, device-side
            else         outFloat[q * TOPK + r] = (float)idx;
        }
        __syncthreads();
    }
}

// ---------------------------------------------------------------------------
// g_newctx[q] = mean of the 32 bank rows selected in g_cixs[q].
// g_cixs / g_newctx referenced from device code only.
__global__ void mean_kernel(const float* __restrict__ bank)
{
    const int q = blockIdx.x;
    const int d = threadIdx.x;
    float s = 0.f;
    #pragma unroll
    for (int j = 0; j < TOPK; ++j)
        s += bank[(size_t)g_cixs[q * TOPK + j] * DIM + d];
    g_newctx[q * DIM + d] = s * (1.0f / 32.0f);
}

// ---------------------------------------------------------------------------
extern "C" void kernel_launch(void* const* d_in, const int* in_sizes, int n_in,
                              void* d_out, int out_size)
{
    // Inputs by element count; the two same-size banks in appearance order =
    // setup_inputs dict order: contexts, enc_ans, enc_ctx, k.
    const float* contexts = nullptr;
    const float* enc_ans  = nullptr;
    const float* enc_ctx  = nullptr;
    for (int i = 0; i < n_in; ++i) {
        if (in_sizes[i] == NQ * DIM) {
            contexts = (const float*)d_in[i];
        } else if (in_sizes[i] == NBANK * DIM) {
            if (!enc_ans) enc_ans = (const float*)d_in[i];
            else          enc_ctx = (const float*)d_in[i];
        }
    }
    if (!contexts && n_in >= 1) contexts = (const float*)d_in[0];
    if (!enc_ans  && n_in >= 2) enc_ans  = (const float*)d_in[1];
    if (!enc_ctx  && n_in >= 3) enc_ctx  = (const float*)d_in[2];

    dim3 ggrid((NBANK + TILE_N - 1) / TILE_N, NQ / TILE_M);

    // Hop 1: contexts vs context bank -> g_sims -> g_cixs (device-side write)
    gemm_kernel<<<ggrid, GT>>>(contexts, enc_ctx, NBANK, 0);
    topk_kernel<<<NQ, 256>>>(nullptr, NBANK, 1);
    // Gather + mean -> g_newctx
    mean_kernel<<<NQ, DIM>>>(enc_ctx);
    // Hop 2: averaged contexts vs answer bank -> g_sims -> d_out as FLOAT
    gemm_kernel<<<ggrid, GT>>>(nullptr, enc_ans, NBANK, 1);
    topk_kernel<<<NQ, 256>>>((float*)d_out, NBANK, 0);
}

// round 15
// speedup vs baseline: 1.7016x; 1.7016x over previous
#include <cuda_runtime.h>
#include <cstdint>

typedef unsigned int u32;
typedef unsigned long long u64;

#define NQ    256
#define DIM   128
#define NBANK 500000
#define TOPK  32

#define TM    64          // q rows per block
#define TN    128         // n rows per block
#define KS    32          // K slice per stage
#define GT    256
#define PADK  36          // KS + 4 floats pad

// -------- device scratch (static; allocation-free per harness rules) --------
// ONLY referenced from device code (host-passing a __device__ symbol was the
// R10-R12 bug: ATS shadow writes).
__device__ float g_sims[(size_t)NQ * NBANK];   // 512 MB
__device__ float g_newctx[NQ * DIM];
__device__ int   g_cixs[NQ * TOPK];

// ---------------------------------------------------------------------------
__device__ __forceinline__ u64 mkkey(float v, u32 n) {
    u32 u = __float_as_uint(v);
    u = (u & 0x80000000u) ? ~u : (u | 0x80000000u);   // monotonic float key
    return ((u64)u << 32) | (u32)(~n);                // ties: smaller idx wins
}
__device__ __forceinline__ void ffma2(u64& d, u64 a, u64 b) {
    asm("fma.rn.f32x2 %0, %1, %2, %0;" : "+l"(d) : "l"(a), "l"(b));
}

// ---------------------------------------------------------------------------
// g_sims[q][n] = sum_d A[q][d]*B[n][d], f32x2 packed along K (u64 acc holds
// even/odd-K partial sums; horizontal add in epilogue).
// Warp w owns q = q0 + 8w .. +7 (A reads are warp-uniform broadcasts);
// lane owns n = n0 + lane + 32j, j=0..3 (B reads conflict-free dense).
__global__ __launch_bounds__(GT, 2)
void gemm_kernel(const float* __restrict__ Aparam, const float* __restrict__ B,
                 int n_rows, int useNewCtx)
{
    __shared__ float Af[TM * PADK];   //  9,216 B
    __shared__ float Bf[TN * PADK];   // 18,432 B

    const float* A = useNewCtx ? g_newctx : Aparam;

    const int tid  = threadIdx.x;
    const int lane = tid & 31;
    const int w    = tid >> 5;             // warp 0..7 -> q group
    const int n0   = blockIdx.x * TN;
    const int q0   = blockIdx.y * TM;

    u64 acc[8][4];
    #pragma unroll
    for (int i = 0; i < 8; ++i)
        #pragma unroll
        for (int j = 0; j < 4; ++j) acc[i][j] = 0ull;

    for (int ks = 0; ks < DIM / KS; ++ks) {          // 4 K stages of 32
        const int kb = ks * KS;
        __syncthreads();
        #pragma unroll
        for (int it = 0; it < 2; ++it) {             // A slice 64x32
            int idx = tid + GT * it;                 // 0..511 float4 slots
            int r = idx >> 3, c4 = idx & 7;
            float4 v = *(const float4*)(A + (size_t)(q0 + r) * DIM + kb + 4 * c4);
            *(float4*)(Af + r * PADK + 4 * c4) = v;
        }
        #pragma unroll
        for (int it = 0; it < 4; ++it) {             // B slice 128x32, padded
            int idx = tid + GT * it;                 // 0..1023
            int r = idx >> 3, c4 = idx & 7;
            float4 v = make_float4(0.f, 0.f, 0.f, 0.f);
            if (n0 + r < n_rows)
                v = *(const float4*)(B + (size_t)(n0 + r) * DIM + kb + 4 * c4);
            *(float4*)(Bf + r * PADK + 4 * c4) = v;
        }
        __syncthreads();

        #pragma unroll
        for (int k4 = 0; k4 < KS / 4; ++k4) {        // 4 K values per step
            ulonglong2 b[4];
            #pragma unroll
            for (int j = 0; j < 4; ++j)
                b[j] = *(const ulonglong2*)(Bf + (lane + 32 * j) * PADK + 4 * k4);
            #pragma unroll
            for (int i = 0; i < 8; ++i) {
                ulonglong2 a = *(const ulonglong2*)(Af + (w * 8 + i) * PADK + 4 * k4);
                #pragma unroll
                for (int j = 0; j < 4; ++j) {
                    ffma2(acc[i][j], a.x, b[j].x);   // K pair (4k4, 4k4+1)
                    ffma2(acc[i][j], a.y, b[j].y);   // K pair (4k4+2, 4k4+3)
                }
            }
        }
    }

    // epilogue: horizontal add, direct coalesced store (lane -> consecutive n)
    #pragma unroll
    for (int i = 0; i < 8; ++i) {
        const size_t qoff = (size_t)(q0 + w * 8 + i) * n_rows;
        #pragma unroll
        for (int j = 0; j < 4; ++j) {
            int gn = n0 + lane + 32 * j;
            if (gn < n_rows) {
                float lo = __uint_as_float((u32)(acc[i][j] & 0xffffffffu));
                float hi = __uint_as_float((u32)(acc[i][j] >> 32));
                g_sims[qoff + gn] = lo + hi;
            }
        }
    }
}

// ---------------------------------------------------------------------------
// Exact per-query top-32 of g_sims row blockIdx.x. 256 threads. (Known-good
// from R13; unchanged this round.)
// useCixs==1 -> int32 indices into device-global g_cixs (hop 1).
// useCixs==0 -> (float)index into outFloat = d_out (hop 2; harness validates
//               d_out as float32).
__global__ __launch_bounds__(256)
void topk_kernel(float* __restrict__ outFloat, int n_rows, int useCixs)
{
    const int q   = blockIdx.x;
    const int tid = threadIdx.x;
    const float4* row = (const float4*)(g_sims + (size_t)q * n_rows);
    const int n4 = n_rows >> 2;           // 500000/4 = 125000 exact

    u64 loc[TOPK];                        // unsorted local top-32 + tracked min
    #pragma unroll
    for (int j = 0; j < TOPK; ++j) loc[j] = 0ull;
    u64 kmin = 0ull;
    int minpos = 0;

    for (int i = tid; i < n4; i += 256) {
        float4 v = row[i];
        u32 base = (u32)i << 2;
        float vv[4] = {v.x, v.y, v.z, v.w};
        #pragma unroll
        for (int c = 0; c < 4; ++c) {
            u64 key = mkkey(vv[c], base + c);
            if (key > kmin) {
                loc[minpos] = key;
                kmin = loc[0]; minpos = 0;
                #pragma unroll
                for (int j = 1; j < TOPK; ++j)
                    if (loc[j] < kmin) { kmin = loc[j]; minpos = j; }
            }
        }
    }

    __shared__ u64 red[256];              // 32 rounds of block max-extraction
    for (int r = 0; r < TOPK; ++r) {
        u64 mymax = loc[0]; int mp = 0;
        #pragma unroll
        for (int j = 1; j < TOPK; ++j)
            if (loc[j] > mymax) { mymax = loc[j]; mp = j; }
        red[tid] = mymax;
        __syncthreads();
        for (int s = 128; s > 0; s >>= 1) {
            if (tid < s) { u64 o = red[tid + s]; if (o > red[tid]) red[tid] = o; }
            __syncthreads();
        }
        u64 win = red[0];
        __syncthreads();
        if (mymax == win) loc[mp] = 0ull; // keys unique -> exactly one remover
        if (tid == 0) {
            int idx = (int)(~(u32)(win & 0xffffffffu));
            if (useCixs) g_cixs[q * TOPK + r] = idx;   // device-side only
            else         outFloat[q * TOPK + r] = (float)idx;
        }
        __syncthreads();
    }
}

// ---------------------------------------------------------------------------
// g_newctx[q] = mean of the 32 bank rows selected in g_cixs[q].
__global__ void mean_kernel(const float* __restrict__ bank)
{
    const int q = blockIdx.x;
    const int d = threadIdx.x;
    float s = 0.f;
    #pragma unroll
    for (int j = 0; j < TOPK; ++j)
        s += bank[(size_t)g_cixs[q * TOPK + j] * DIM + d];
    g_newctx[q * DIM + d] = s * (1.0f / 32.0f);
}

// ---------------------------------------------------------------------------
extern "C" void kernel_launch(void* const* d_in, const int* in_sizes, int n_in,
                              void* d_out, int out_size)
{
    // Inputs by element count; the two same-size banks in appearance order =
    // setup_inputs dict order: contexts, enc_ans, enc_ctx, k.
    const float* contexts = nullptr;
    const float* enc_ans  = nullptr;
    const float* enc_ctx  = nullptr;
    for (int i = 0; i < n_in; ++i) {
        if (in_sizes[i] == NQ * DIM) {
            contexts = (const float*)d_in[i];
        } else if (in_sizes[i] == NBANK * DIM) {
            if (!enc_ans) enc_ans = (const float*)d_in[i];
            else          enc_ctx = (const float*)d_in[i];
        }
    }
    if (!contexts && n_in >= 1) contexts = (const float*)d_in[0];
    if (!enc_ans  && n_in >= 2) enc_ans  = (const float*)d_in[1];
    if (!enc_ctx  && n_in >= 3) enc_ctx  = (const float*)d_in[2];

    dim3 ggrid((NBANK + TN - 1) / TN, NQ / TM);

    // Hop 1: contexts vs context bank -> g_sims -> g_cixs
    gemm_kernel<<<ggrid, GT>>>(contexts, enc_ctx, NBANK, 0);
    topk_kernel<<<NQ, 256>>>(nullptr, NBANK, 1);
    // Gather + mean -> g_newctx
    mean_kernel<<<NQ, DIM>>>(enc_ctx);
    // Hop 2: averaged contexts vs answer bank -> g_sims -> d_out as FLOAT
    gemm_kernel<<<ggrid, GT>>>(nullptr, enc_ans, NBANK, 1);
    topk_kernel<<<NQ, 256>>>((float*)d_out, NBANK, 0);
}

// round 16
// speedup vs baseline: 4.7949x; 2.8179x over previous
#include <cuda_runtime.h>
#include <cstdint>

typedef unsigned int u32;
typedef unsigned long long u64;

#define NQ    256
#define DIM   128
#define NBANK 500000
#define TOPK  32

#define TM    64          // q rows per block
#define TN    128         // n rows per block
#define KS    32          // K slice per stage
#define GT    256
#define PADK  36          // KS + 4 floats pad
#define CAP   4096        // per-query candidate capacity

// -------- device scratch (device-code-referenced ONLY; R12 lesson) ---------
__device__ float g_newctx[NQ * DIM];
__device__ int   g_cixs[NQ * TOPK];
__device__ float g_tau[NQ];
__device__ u32   g_cnt[NQ];
__device__ u64   g_cand[(size_t)NQ * CAP];     // 8 MB

// ---------------------------------------------------------------------------
__device__ __forceinline__ u64 mkkey(float v, u32 n) {
    u32 u = __float_as_uint(v);
    u = (u & 0x80000000u) ? ~u : (u | 0x80000000u);   // monotonic float key
    return ((u64)u << 32) | (u32)(~n);                // ties: smaller idx wins
}
__device__ __forceinline__ void ffma2(u64& d, u64 a, u64 b) {
    asm("fma.rn.f32x2 %0, %1, %2, %0;" : "+l"(d) : "l"(a), "l"(b));
}

// ---------------------------------------------------------------------------
// Per-query threshold tau = 3*||A_q|| and candidate-count reset. 128 threads.
__global__ void prep_kernel(const float* __restrict__ Aparam, int useNewCtx)
{
    const float* A = useNewCtx ? g_newctx : Aparam;
    const int q = blockIdx.x, d = threadIdx.x;
    __shared__ float s[4];
    float x = A[(size_t)q * DIM + d];
    float v = x * x;
    #pragma unroll
    for (int off = 16; off; off >>= 1) v += __shfl_down_sync(0xffffffffu, v, off);
    if ((d & 31) == 0) s[d >> 5] = v;
    __syncthreads();
    if (d == 0) {
        g_tau[q] = 3.0f * sqrtf(s[0] + s[1] + s[2] + s[3]);
        g_cnt[q] = 0u;
    }
}

// ---------------------------------------------------------------------------
// GEMM with fused candidate filter. Inner loop identical to the passing R15
// kernel; epilogue appends values > tau[q] to g_cand instead of writing sims.
__global__ __launch_bounds__(GT, 2)
void gemm_kernel(const float* __restrict__ Aparam, const float* __restrict__ B,
                 int n_rows, int useNewCtx)
{
    __shared__ float Af[TM * PADK];
    __shared__ float Bf[TN * PADK];

    const float* A = useNewCtx ? g_newctx : Aparam;

    const int tid  = threadIdx.x;
    const int lane = tid & 31;
    const int w    = tid >> 5;
    const int n0   = blockIdx.x * TN;
    const int q0   = blockIdx.y * TM;

    u64 acc[8][4];
    #pragma unroll
    for (int i = 0; i < 8; ++i)
        #pragma unroll
        for (int j = 0; j < 4; ++j) acc[i][j] = 0ull;

    for (int ks = 0; ks < DIM / KS; ++ks) {
        const int kb = ks * KS;
        __syncthreads();
        #pragma unroll
        for (int it = 0; it < 2; ++it) {
            int idx = tid + GT * it;
            int r = idx >> 3, c4 = idx & 7;
            float4 v = *(const float4*)(A + (size_t)(q0 + r) * DIM + kb + 4 * c4);
            *(float4*)(Af + r * PADK + 4 * c4) = v;
        }
        #pragma unroll
        for (int it = 0; it < 4; ++it) {
            int idx = tid + GT * it;
            int r = idx >> 3, c4 = idx & 7;
            float4 v = make_float4(0.f, 0.f, 0.f, 0.f);
            if (n0 + r < n_rows)
                v = *(const float4*)(B + (size_t)(n0 + r) * DIM + kb + 4 * c4);
            *(float4*)(Bf + r * PADK + 4 * c4) = v;
        }
        __syncthreads();

        #pragma unroll
        for (int k4 = 0; k4 < KS / 4; ++k4) {
            ulonglong2 b[4];
            #pragma unroll
            for (int j = 0; j < 4; ++j)
                b[j] = *(const ulonglong2*)(Bf + (lane + 32 * j) * PADK + 4 * k4);
            #pragma unroll
            for (int i = 0; i < 8; ++i) {
                ulonglong2 a = *(const ulonglong2*)(Af + (w * 8 + i) * PADK + 4 * k4);
                #pragma unroll
                for (int j = 0; j < 4; ++j) {
                    ffma2(acc[i][j], a.x, b[j].x);
                    ffma2(acc[i][j], a.y, b[j].y);
                }
            }
        }
    }

    // epilogue: horizontal add + threshold filter (expected ~4 hits/block)
    #pragma unroll
    for (int i = 0; i < 8; ++i) {
        const int q = q0 + w * 8 + i;
        const float tau = g_tau[q];
        #pragma unroll
        for (int j = 0; j < 4; ++j) {
            float lo = __uint_as_float((u32)(acc[i][j] & 0xffffffffu));
            float hi = __uint_as_float((u32)(acc[i][j] >> 32));
            float v  = lo + hi;
            int   gn = n0 + lane + 32 * j;
            if (v > tau && gn < n_rows) {
                u32 pos = atomicAdd(&g_cnt[q], 1u);
                if (pos < CAP) g_cand[(size_t)q * CAP + pos] = mkkey(v, (u32)gn);
            }
        }
    }
}

// ---------------------------------------------------------------------------
// Exact per-query top-32 from candidates; full-recompute fallback if the
// threshold path can't guarantee exactness (cnt<32 or overflow). 256 threads.
__global__ __launch_bounds__(256)
void final_topk(const float* __restrict__ Aparam, const float* __restrict__ B,
                float* __restrict__ outFloat, int useCixs, int useNewCtx)
{
    const int q   = blockIdx.x;
    const int tid = threadIdx.x;
    const u32 cnt = g_cnt[q];

    __shared__ u64 red[256];

    if (cnt >= TOPK && cnt <= CAP) {
        // ---- normal path: top-32 of cnt candidates (all values > tau) ----
        u64 mine[CAP / 256];
        int m = 0;
        for (u32 i = tid; i < cnt; i += 256) mine[m++] = g_cand[(size_t)q * CAP + i];

        for (int r = 0; r < TOPK; ++r) {
            u64 mymax = 0ull; int mp = -1;
            for (int jj = 0; jj < m; ++jj)
                if (mine[jj] > mymax) { mymax = mine[jj]; mp = jj; }
            red[tid] = mymax;
            __syncthreads();
            for (int s = 128; s > 0; s >>= 1) {
                if (tid < s) { u64 o = red[tid + s]; if (o > red[tid]) red[tid] = o; }
                __syncthreads();
            }
            u64 win = red[0];
            __syncthreads();
            if (mp >= 0 && mymax == win) mine[mp] = 0ull;  // unique keys
            if (tid == 0) {
                int idx = (int)(~(u32)(win & 0xffffffffu));
                if (useCixs) g_cixs[q * TOPK + r] = idx;
                else         outFloat[q * TOPK + r] = (float)idx;
            }
            __syncthreads();
        }
    } else {
        // ---- fallback (exactness safety; statistically never taken) ----
        __shared__ float qrow[DIM];
        const float* A = useNewCtx ? g_newctx : Aparam;
        for (int d = tid; d < DIM; d += 256) qrow[d] = A[(size_t)q * DIM + d];
        __syncthreads();

        u64 loc[TOPK];
        #pragma unroll
        for (int j = 0; j < TOPK; ++j) loc[j] = 0ull;
        u64 kmin = 0ull; int minpos = 0;

        for (int n = tid; n < NBANK; n += 256) {
            const float4* br = (const float4*)(B + (size_t)n * DIM);
            float s = 0.f;
            #pragma unroll
            for (int c = 0; c < DIM / 4; ++c) {
                float4 b = br[c];
                s += qrow[4 * c] * b.x + qrow[4 * c + 1] * b.y
                   + qrow[4 * c + 2] * b.z + qrow[4 * c + 3] * b.w;
            }
            u64 key = mkkey(s, (u32)n);
            if (key > kmin) {
                loc[minpos] = key;
                kmin = loc[0]; minpos = 0;
                #pragma unroll
                for (int j = 1; j < TOPK; ++j)
                    if (loc[j] < kmin) { kmin = loc[j]; minpos = j; }
            }
        }
        for (int r = 0; r < TOPK; ++r) {
            u64 mymax = loc[0]; int mp = 0;
            #pragma unroll
            for (int j = 1; j < TOPK; ++j)
                if (loc[j] > mymax) { mymax = loc[j]; mp = j; }
            red[tid] = mymax;
            __syncthreads();
            for (int s = 128; s > 0; s >>= 1) {
                if (tid < s) { u64 o = red[tid + s]; if (o > red[tid]) red[tid] = o; }
                __syncthreads();
            }
            u64 win = red[0];
            __syncthreads();
            if (mymax == win) loc[mp] = 0ull;
            if (tid == 0) {
                int idx = (int)(~(u32)(win & 0xffffffffu));
                if (useCixs) g_cixs[q * TOPK + r] = idx;
                else         outFloat[q * TOPK + r] = (float)idx;
            }
            __syncthreads();
        }
    }
}

// ---------------------------------------------------------------------------
__global__ void mean_kernel(const float* __restrict__ bank)
{
    const int q = blockIdx.x;
    const int d = threadIdx.x;
    float s = 0.f;
    #pragma unroll
    for (int j = 0; j < TOPK; ++j)
        s += bank[(size_t)g_cixs[q * TOPK + j] * DIM + d];
    g_newctx[q * DIM + d] = s * (1.0f / 32.0f);
}

// ---------------------------------------------------------------------------
extern "C" void kernel_launch(void* const* d_in, const int* in_sizes, int n_in,
                              void* d_out, int out_size)
{
    // Inputs by element count; same-size banks in appearance order =
    // setup_inputs dict order: contexts, enc_ans, enc_ctx, k. (Proven R13.)
    const float* contexts = nullptr;
    const float* enc_ans  = nullptr;
    const float* enc_ctx  = nullptr;
    for (int i = 0; i < n_in; ++i) {
        if (in_sizes[i] == NQ * DIM) {
            contexts = (const float*)d_in[i];
        } else if (in_sizes[i] == NBANK * DIM) {
            if (!enc_ans) enc_ans = (const float*)d_in[i];
            else          enc_ctx = (const float*)d_in[i];
        }
    }
    if (!contexts && n_in >= 1) contexts = (const float*)d_in[0];
    if (!enc_ans  && n_in >= 2) enc_ans  = (const float*)d_in[1];
    if (!enc_ctx  && n_in >= 3) enc_ctx  = (const float*)d_in[2];

    dim3 ggrid((NBANK + TN - 1) / TN, NQ / TM);

    // Hop 1: contexts vs context bank -> candidates -> g_cixs
    prep_kernel<<<NQ, DIM>>>(contexts, 0);
    gemm_kernel<<<ggrid, GT>>>(contexts, enc_ctx, NBANK, 0);
    final_topk<<<NQ, 256>>>(contexts, enc_ctx, nullptr, 1, 0);
    // Gather + mean -> g_newctx
    mean_kernel<<<NQ, DIM>>>(enc_ctx);
    // Hop 2: averaged contexts vs answer bank -> candidates -> d_out (float)
    prep_kernel<<<NQ, DIM>>>(nullptr, 1);
    gemm_kernel<<<ggrid, GT>>>(nullptr, enc_ans, NBANK, 1);
    final_topk<<<NQ, 256>>>(nullptr, enc_ans, (float*)d_out, 0, 1);
}